// round 2
// baseline (speedup 1.0000x reference)
#include <cuda_runtime.h>
#include <math.h>

#define NN 30000
#define NP 30080          // 235 * 128, padded rows are zero / never referenced by edges
#define EE 200000
#define FF 256
#define HH 8
#define DD 32
#define LL 3

// ---------------- scratch (static device memory; no allocation) ----------------
__device__ float g_x  [2 * (size_t)NP * FF];        // node features, both types (in-place across layers)
__device__ float g_kqv[2 * (size_t)NP * 3 * FF];    // [type][node][768]
__device__ float g_ke [2 * (size_t)NP * FF];        // per edge-type relation-transformed keys of src type
__device__ float g_ve [2 * (size_t)NP * FF];        // per edge-type relation-transformed values
__device__ float g_agg[2 * (size_t)NP * FF];        // per dst-type aggregation
__device__ float g_sc [2 * (size_t)EE * HH];        // per edge-type scores -> exp values
__device__ float g_m  [2 * (size_t)NP * HH];        // segment max
__device__ float g_z  [2 * (size_t)NP * HH];        // segment sum

__device__ __forceinline__ float gelu_exact(float x) {
    return 0.5f * x * (1.0f + erff(x * 0.70710678118654752440f));
}

__device__ __forceinline__ void atomicMaxFloat(float* addr, float val) {
    if (val >= 0.0f) atomicMax((int*)addr, __float_as_int(val));
    else             atomicMin((unsigned int*)addr, __float_as_uint(val));
}

// ---------------- copies ----------------
__global__ void copy_in_kernel(const float* __restrict__ x0, const float* __restrict__ x1) {
    size_t i = (size_t)blockIdx.x * 256 + threadIdx.x;
    if (i < (size_t)NN * FF) {
        g_x[i] = x0[i];
        g_x[(size_t)NP * FF + i] = x1[i];
    }
}

__global__ void copy_out_kernel(float* __restrict__ out) {
    size_t i = (size_t)blockIdx.x * 256 + threadIdx.x;
    if (i < (size_t)NN * FF) {
        out[i] = g_x[i];
        out[(size_t)NN * FF + i] = g_x[(size_t)NP * FF + i];
    }
}

// ---------------- per-layer init ----------------
__global__ void init_kernel() {
    size_t i = (size_t)blockIdx.x * 256 + threadIdx.x;
    if (i < 2 * (size_t)NP * FF) g_agg[i] = 0.0f;
    if (i < 2 * (size_t)NP * HH) { g_m[i] = -INFINITY; g_z[i] = 0.0f; }
}

// ---------------- SGEMM: C[M,Nc] = op(A)[M,K] @ B[K,Nc] + bias (+ epilogue) ----------------
// BM=BN=128, BK=8, 256 threads, 8x8 per thread. M (grid.y*128) is padded; K,Nc multiples of 8/128.
template <bool GELU_A, bool EPI>
__global__ void __launch_bounds__(256) gemm_kernel(
    const float* __restrict__ A, const float* __restrict__ B,
    const float* __restrict__ bias, float* __restrict__ C,
    int K, int Nc, const float* __restrict__ xres, const float* __restrict__ skp)
{
    __shared__ float As[8][128];
    __shared__ float Bs[8][128];
    const int tid = threadIdx.x;
    const int m0 = blockIdx.y * 128;
    const int n0 = blockIdx.x * 128;
    const int tx = tid & 15;
    const int ty = tid >> 4;

    float acc[8][8];
#pragma unroll
    for (int i = 0; i < 8; i++)
#pragma unroll
        for (int j = 0; j < 8; j++) acc[i][j] = 0.0f;

    const int aRow = tid >> 1;
    const int aK   = (tid & 1) * 4;
    const int bRow = tid >> 5;
    const int bCol = (tid & 31) * 4;
    const float* Ap = A + (size_t)(m0 + aRow) * K + aK;
    const float* Bp = B + (size_t)bRow * Nc + n0 + bCol;

    for (int k0 = 0; k0 < K; k0 += 8) {
        float4 av = *(const float4*)(Ap + k0);
        float4 bv = *(const float4*)(Bp + (size_t)k0 * Nc);
        if (GELU_A) {
            av.x = gelu_exact(av.x); av.y = gelu_exact(av.y);
            av.z = gelu_exact(av.z); av.w = gelu_exact(av.w);
        }
        __syncthreads();
        As[aK + 0][aRow] = av.x; As[aK + 1][aRow] = av.y;
        As[aK + 2][aRow] = av.z; As[aK + 3][aRow] = av.w;
        *(float4*)&Bs[bRow][bCol] = bv;
        __syncthreads();
#pragma unroll
        for (int k = 0; k < 8; k++) {
            float ar[8], br[8];
            *(float4*)(ar)     = *(const float4*)&As[k][ty * 8];
            *(float4*)(ar + 4) = *(const float4*)&As[k][ty * 8 + 4];
            *(float4*)(br)     = *(const float4*)&Bs[k][tx * 8];
            *(float4*)(br + 4) = *(const float4*)&Bs[k][tx * 8 + 4];
#pragma unroll
            for (int i = 0; i < 8; i++)
#pragma unroll
                for (int j = 0; j < 8; j++)
                    acc[i][j] = fmaf(ar[i], br[j], acc[i][j]);
        }
    }

    float sA = 0.0f;
    if (EPI) sA = 1.0f / (1.0f + __expf(-skp[0]));
#pragma unroll
    for (int i = 0; i < 8; i++) {
        int m = m0 + ty * 8 + i;
#pragma unroll
        for (int j = 0; j < 8; j++) {
            int n = n0 + tx * 8 + j;
            float o = acc[i][j] + bias[n];
            if (EPI) {
                o = sA * o + (1.0f - sA) * xres[(size_t)m * FF + n];
                o = fmaxf(o, 0.0f);
            }
            C[(size_t)m * Nc + n] = o;
        }
    }
}

// ---------------- relation transform: out[n,h,:] = in[n,h,:] @ Amat[h] ----------------
// in: rows stride 768 (k at +0, v at +512 within kqv row). out: stride 256. 16 nodes/block.
__global__ void __launch_bounds__(256) rel_kernel(
    const float* __restrict__ in, const float* __restrict__ Amat, float* __restrict__ out)
{
    __shared__ float sA[HH * DD * DD];   // 32 KB
    __shared__ float sk[16][FF];         // 16 KB
    const int tid = threadIdx.x;
    for (int i = tid; i < HH * DD * DD; i += 256) sA[i] = Amat[i];
    const int nodeBase = blockIdx.x * 16;
    for (int i = tid; i < 16 * FF; i += 256) {
        int r = i >> 8, c = i & 255;
        sk[r][c] = in[(size_t)(nodeBase + r) * 768 + c];
    }
    __syncthreads();
    const int h = tid >> 5;
    const int e = tid & 31;
    const float* Ah = &sA[h * DD * DD];
#pragma unroll 4
    for (int r = 0; r < 16; r++) {
        float accv = 0.0f;
#pragma unroll
        for (int d0 = 0; d0 < DD; d0++)
            accv = fmaf(sk[r][h * 32 + d0], Ah[d0 * DD + e], accv);
        out[(size_t)(nodeBase + r) * FF + h * 32 + e] = accv;
    }
}

// ---------------- edge pass 1: scores + segment max (one warp per edge) ----------------
__global__ void __launch_bounds__(256) score_kernel(
    const float* __restrict__ kqv_dt, const float* __restrict__ ke,
    const int* __restrict__ src, const int* __restrict__ dst,
    const float* __restrict__ p, float* __restrict__ sc, float* __restrict__ m)
{
    int wid = (blockIdx.x * blockDim.x + threadIdx.x) >> 5;
    if (wid >= EE) return;
    int lane = threadIdx.x & 31;
    int s = src[wid], d = dst[wid];
    const float* qr = kqv_dt + (size_t)d * 768 + 256;
    const float* kr = ke + (size_t)s * 256;
#pragma unroll
    for (int h = 0; h < HH; h++) {
        float v = qr[h * 32 + lane] * kr[h * 32 + lane];
        v += __shfl_xor_sync(0xffffffffu, v, 16);
        v += __shfl_xor_sync(0xffffffffu, v, 8);
        v += __shfl_xor_sync(0xffffffffu, v, 4);
        v += __shfl_xor_sync(0xffffffffu, v, 2);
        v += __shfl_xor_sync(0xffffffffu, v, 1);
        if (lane == 0) {
            float scv = v * p[h] * 0.17677669529663688110f;  // 1/sqrt(32)
            sc[(size_t)wid * HH + h] = scv;
            atomicMaxFloat(&m[(size_t)d * HH + h], scv);
        }
    }
}

// ---------------- edge pass 2: exp + segment sum ----------------
__global__ void __launch_bounds__(256) exp_kernel(
    const int* __restrict__ dst, float* __restrict__ sc,
    const float* __restrict__ m, float* __restrict__ z)
{
    size_t idx = (size_t)blockIdx.x * 256 + threadIdx.x;
    if (idx >= (size_t)EE * HH) return;
    int e = (int)(idx >> 3);
    int h = (int)(idx & 7);
    int d = dst[e];
    float ev = __expf(sc[idx] - m[(size_t)d * HH + h]);
    sc[idx] = ev;
    atomicAdd(&z[(size_t)d * HH + h], ev);
}

// ---------------- edge pass 3: normalize + aggregate (one warp per edge) ----------------
__global__ void __launch_bounds__(256) agg_kernel(
    const float* __restrict__ ve, const int* __restrict__ src, const int* __restrict__ dst,
    const float* __restrict__ sc, const float* __restrict__ z, float* __restrict__ agg)
{
    int wid = (blockIdx.x * blockDim.x + threadIdx.x) >> 5;
    if (wid >= EE) return;
    int lane = threadIdx.x & 31;
    int s = src[wid], d = dst[wid];
    const float* vr = ve + (size_t)s * 256;
    float* ar = agg + (size_t)d * 256;
#pragma unroll
    for (int h = 0; h < HH; h++) {
        float alpha = sc[(size_t)wid * HH + h] / z[(size_t)d * HH + h];
        atomicAdd(&ar[h * 32 + lane], vr[h * 32 + lane] * alpha);
    }
}

// ---------------- driver ----------------
extern "C" void kernel_launch(void* const* d_in, const int* in_sizes, int n_in,
                              void* d_out, int out_size)
{
    const float* x0 = (const float*)d_in[0];
    const float* x1 = (const float*)d_in[1];
    const int*   e_dr = (const int*)d_in[2];   // [2,E] row0=src(drug) row1=dst(react)
    const int*   e_rd = (const int*)d_in[3];
    const float* Wk = (const float*)d_in[4];   // [L,2,F,3F]
    const float* bk = (const float*)d_in[5];   // [L,2,3F]
    const float* Ar = (const float*)d_in[6];   // [L,2,H,D,D]
    const float* Mr = (const float*)d_in[7];
    const float* pr = (const float*)d_in[8];   // [L,2,H]
    const float* Wo = (const float*)d_in[9];   // [L,2,F,F]
    const float* bo = (const float*)d_in[10];  // [L,2,F]
    const float* sk = (const float*)d_in[11];  // [L,2]
    float* out = (float*)d_out;

    float *gx, *gkqv, *gke, *gve, *gagg, *gsc, *gm, *gz;
    cudaGetSymbolAddress((void**)&gx,   g_x);
    cudaGetSymbolAddress((void**)&gkqv, g_kqv);
    cudaGetSymbolAddress((void**)&gke,  g_ke);
    cudaGetSymbolAddress((void**)&gve,  g_ve);
    cudaGetSymbolAddress((void**)&gagg, g_agg);
    cudaGetSymbolAddress((void**)&gsc,  g_sc);
    cudaGetSymbolAddress((void**)&gm,   g_m);
    cudaGetSymbolAddress((void**)&gz,   g_z);

    const int copyBlocks = (NN * FF + 255) / 256;
    copy_in_kernel<<<copyBlocks, 256>>>(x0, x1);

    for (int l = 0; l < LL; l++) {
        init_kernel<<<(2 * NP * FF + 255) / 256, 256>>>();

        // kqv = x @ Wk + bk
        for (int t = 0; t < 2; t++) {
            gemm_kernel<false, false><<<dim3(768 / 128, NP / 128), 256>>>(
                gx + (size_t)t * NP * FF,
                Wk + ((size_t)(l * 2 + t)) * FF * 3 * FF,
                bk + (size_t)(l * 2 + t) * 3 * FF,
                gkqv + (size_t)t * NP * 3 * FF,
                FF, 3 * FF, nullptr, nullptr);
        }

        // relation transforms: et=0: src type 0; et=1: src type 1
        for (int et = 0; et < 2; et++) {
            int st = et;
            const float* kqv_st = gkqv + (size_t)st * NP * 3 * FF;
            rel_kernel<<<NP / 16, 256>>>(kqv_st,       Ar + (size_t)(l * 2 + et) * HH * DD * DD,
                                         gke + (size_t)et * NP * FF);
            rel_kernel<<<NP / 16, 256>>>(kqv_st + 512, Mr + (size_t)(l * 2 + et) * HH * DD * DD,
                                         gve + (size_t)et * NP * FF);
        }

        // edge passes
        for (int et = 0; et < 2; et++) {
            int dt = 1 - et;
            const int* ei = (et == 0) ? e_dr : e_rd;
            score_kernel<<<EE / 8, 256>>>(
                gkqv + (size_t)dt * NP * 3 * FF,
                gke + (size_t)et * NP * FF,
                ei, ei + EE,
                pr + (size_t)(l * 2 + et) * HH,
                gsc + (size_t)et * EE * HH,
                gm + (size_t)dt * NP * HH);
        }
        for (int et = 0; et < 2; et++) {
            int dt = 1 - et;
            const int* ei = (et == 0) ? e_dr : e_rd;
            exp_kernel<<<(EE * HH + 255) / 256, 256>>>(
                ei + EE,
                gsc + (size_t)et * EE * HH,
                gm + (size_t)dt * NP * HH,
                gz + (size_t)dt * NP * HH);
        }
        for (int et = 0; et < 2; et++) {
            int dt = 1 - et;
            const int* ei = (et == 0) ? e_dr : e_rd;
            agg_kernel<<<EE / 8, 256>>>(
                gve + (size_t)et * NP * FF,
                ei, ei + EE,
                gsc + (size_t)et * EE * HH,
                gz + (size_t)dt * NP * HH,
                gagg + (size_t)dt * NP * FF);
        }

        // out = relu( a*(gelu(agg) @ Wo + bo) + (1-a)*x )   (in place on x)
        for (int t = 0; t < 2; t++) {
            gemm_kernel<true, true><<<dim3(FF / 128, NP / 128), 256>>>(
                gagg + (size_t)t * NP * FF,
                Wo + (size_t)(l * 2 + t) * FF * FF,
                bo + (size_t)(l * 2 + t) * FF,
                gx + (size_t)t * NP * FF,
                FF, FF,
                gx + (size_t)t * NP * FF,
                sk + (l * 2 + t));
        }
    }

    copy_out_kernel<<<copyBlocks, 256>>>(out);
}

// round 4
// speedup vs baseline: 1.2039x; 1.2039x over previous
#include <cuda_runtime.h>
#include <math.h>

#define NN 30000
#define NP 30080          // 235 * 128, padded rows are zero / never referenced by edges
#define EE 200000
#define FF 256
#define HH 8
#define DD 32
#define LL 3

// ---------------- scratch (static device memory; no allocation) ----------------
__device__ float g_x  [2 * (size_t)NP * FF];        // node features, both types (in-place across layers)
__device__ float g_kqv[2 * (size_t)NP * 3 * FF];    // [type][node][768]
__device__ float g_ke [2 * (size_t)NP * FF];        // per edge-type relation-transformed keys of src type
__device__ float g_ve [2 * (size_t)NP * FF];        // per edge-type relation-transformed values
__device__ float g_agg[2 * (size_t)NP * FF];        // per dst-type aggregation (padded rows stay 0 forever)

// CSR scratch (built once per call; edges are identical across layers)
__device__ int g_deg[2 * NP];
__device__ int g_cur[2 * NP];
__device__ int g_off[2 * (NP + 1)];
__device__ int g_eid[2 * EE];
__device__ int g_srt[2 * EE];

__device__ __forceinline__ float gelu_exact(float x) {
    return 0.5f * x * (1.0f + erff(x * 0.70710678118654752440f));
}

// ---------------- copies ----------------
__global__ void copy_in_kernel(const float* __restrict__ x0, const float* __restrict__ x1) {
    size_t i = (size_t)blockIdx.x * 256 + threadIdx.x;
    if (i < (size_t)NN * FF) {
        g_x[i] = x0[i];
        g_x[(size_t)NP * FF + i] = x1[i];
    }
}

__global__ void copy_out_kernel(float* __restrict__ out) {
    size_t i = (size_t)blockIdx.x * 256 + threadIdx.x;
    if (i < (size_t)NN * FF) {
        out[i] = g_x[i];
        out[(size_t)NN * FF + i] = g_x[(size_t)NP * FF + i];
    }
}

// ---------------- CSR build ----------------
__global__ void csr_zero_kernel() {
    int i = blockIdx.x * 256 + threadIdx.x;
    if (i < 2 * NP) { g_deg[i] = 0; g_cur[i] = 0; }
}

__global__ void csr_hist_kernel(const int* __restrict__ dst0, const int* __restrict__ dst1) {
    int e = blockIdx.x * 256 + threadIdx.x;
    if (e < EE) {
        atomicAdd(&g_deg[dst0[e]], 1);
        atomicAdd(&g_deg[NP + dst1[e]], 1);
    }
}

// exclusive scan per edge type; one block (1024 threads) per type
__global__ void __launch_bounds__(1024) csr_scan_kernel() {
    const int t = blockIdx.x;
    const int* deg = g_deg + t * NP;
    int* off = g_off + t * (NP + 1);
    __shared__ int sm[1024];
    __shared__ int carry_s;
    const int tid = threadIdx.x;
    if (tid == 0) carry_s = 0;
    __syncthreads();
    for (int base = 0; base < NP; base += 1024) {
        int v = (base + tid < NP) ? deg[base + tid] : 0;
        sm[tid] = v;
        __syncthreads();
#pragma unroll
        for (int o = 1; o < 1024; o <<= 1) {
            int y = (tid >= o) ? sm[tid - o] : 0;
            __syncthreads();
            sm[tid] += y;
            __syncthreads();
        }
        int incl = sm[tid];
        if (base + tid < NP) off[base + tid] = carry_s + incl - v;
        __syncthreads();
        if (tid == 1023) carry_s += incl;
        __syncthreads();
    }
    if (tid == 0) off[NP] = carry_s;
}

__global__ void csr_scatter_kernel(const int* __restrict__ dst0, const int* __restrict__ dst1) {
    int e = blockIdx.x * 256 + threadIdx.x;
    if (e >= EE) return;
    int d0 = dst0[e];
    int p0 = g_off[d0] + atomicAdd(&g_cur[d0], 1);
    g_eid[p0] = e;
    int d1 = dst1[e];
    int p1 = g_off[(NP + 1) + d1] + atomicAdd(&g_cur[NP + d1], 1);
    g_eid[EE + p1] = e;
}

// per-dst insertion sort by edge id (determinism) + convert eid -> src
__global__ void csr_sort_kernel(const int* __restrict__ s0, const int* __restrict__ s1) {
    int idx = blockIdx.x * 256 + threadIdx.x;
    if (idx >= 2 * NP) return;
    int t = (idx >= NP) ? 1 : 0;
    int d = idx - t * NP;
    const int* off = g_off + t * (NP + 1);
    int b = off[d], e = off[d + 1];
    int* a = g_eid + t * EE;
    for (int i = b + 1; i < e; i++) {
        int key = a[i];
        int j = i - 1;
        while (j >= b && a[j] > key) { a[j + 1] = a[j]; j--; }
        a[j + 1] = key;
    }
    const int* sarr = t ? s1 : s0;
    int* o = g_srt + t * EE;
    for (int i = b; i < e; i++) o[i] = sarr[a[i]];
}

// ---------------- SGEMM: C[M,Nc] = op(A)[M,K] @ B[K,Nc] + bias (+ epilogue) ----------------
template <bool GELU_A, bool EPI>
__global__ void __launch_bounds__(256) gemm_kernel(
    const float* __restrict__ A, const float* __restrict__ B,
    const float* __restrict__ bias, float* __restrict__ C,
    int K, int Nc, const float* __restrict__ xres, const float* __restrict__ skp)
{
    __shared__ float As[8][128];
    __shared__ float Bs[8][128];
    const int tid = threadIdx.x;
    const int m0 = blockIdx.y * 128;
    const int n0 = blockIdx.x * 128;
    const int tx = tid & 15;
    const int ty = tid >> 4;

    float acc[8][8];
#pragma unroll
    for (int i = 0; i < 8; i++)
#pragma unroll
        for (int j = 0; j < 8; j++) acc[i][j] = 0.0f;

    const int aRow = tid >> 1;
    const int aK   = (tid & 1) * 4;
    const int bRow = tid >> 5;
    const int bCol = (tid & 31) * 4;
    const float* Ap = A + (size_t)(m0 + aRow) * K + aK;
    const float* Bp = B + (size_t)bRow * Nc + n0 + bCol;

    for (int k0 = 0; k0 < K; k0 += 8) {
        float4 av = *(const float4*)(Ap + k0);
        float4 bv = *(const float4*)(Bp + (size_t)k0 * Nc);
        if (GELU_A) {
            av.x = gelu_exact(av.x); av.y = gelu_exact(av.y);
            av.z = gelu_exact(av.z); av.w = gelu_exact(av.w);
        }
        __syncthreads();
        As[aK + 0][aRow] = av.x; As[aK + 1][aRow] = av.y;
        As[aK + 2][aRow] = av.z; As[aK + 3][aRow] = av.w;
        *(float4*)&Bs[bRow][bCol] = bv;
        __syncthreads();
#pragma unroll
        for (int k = 0; k < 8; k++) {
            float ar[8], br[8];
            *(float4*)(ar)     = *(const float4*)&As[k][ty * 8];
            *(float4*)(ar + 4) = *(const float4*)&As[k][ty * 8 + 4];
            *(float4*)(br)     = *(const float4*)&Bs[k][tx * 8];
            *(float4*)(br + 4) = *(const float4*)&Bs[k][tx * 8 + 4];
#pragma unroll
            for (int i = 0; i < 8; i++)
#pragma unroll
                for (int j = 0; j < 8; j++)
                    acc[i][j] = fmaf(ar[i], br[j], acc[i][j]);
        }
    }

    float sA = 0.0f;
    if (EPI) sA = 1.0f / (1.0f + __expf(-skp[0]));
#pragma unroll
    for (int i = 0; i < 8; i++) {
        int m = m0 + ty * 8 + i;
#pragma unroll
        for (int j = 0; j < 8; j++) {
            int n = n0 + tx * 8 + j;
            float o = acc[i][j] + bias[n];
            if (EPI) {
                o = sA * o + (1.0f - sA) * xres[(size_t)m * FF + n];
                o = fmaxf(o, 0.0f);
            }
            C[(size_t)m * Nc + n] = o;
        }
    }
}

// ---------------- relation transform: out[n,h,:] = in[n,h,:] @ Amat[h] ----------------
__global__ void __launch_bounds__(256) rel_kernel(
    const float* __restrict__ in, const float* __restrict__ Amat, float* __restrict__ out)
{
    __shared__ float sA[HH * DD * DD];
    __shared__ float sk[16][FF];
    const int tid = threadIdx.x;
    for (int i = tid; i < HH * DD * DD; i += 256) sA[i] = Amat[i];
    const int nodeBase = blockIdx.x * 16;
    for (int i = tid; i < 16 * FF; i += 256) {
        int r = i >> 8, c = i & 255;
        sk[r][c] = in[(size_t)(nodeBase + r) * 768 + c];
    }
    __syncthreads();
    const int h = tid >> 5;
    const int e = tid & 31;
    const float* Ah = &sA[h * DD * DD];
#pragma unroll 4
    for (int r = 0; r < 16; r++) {
        float accv = 0.0f;
#pragma unroll
        for (int d0 = 0; d0 < DD; d0++)
            accv = fmaf(sk[r][h * 32 + d0], Ah[d0 * DD + e], accv);
        out[(size_t)(nodeBase + r) * FF + h * 32 + e] = accv;
    }
}

// ---------------- fused edge attention: one warp per dst node, online softmax ----------------
// lane layout: h = lane>>2 (head), d-slice = (lane&3)*8 .. +8
__global__ void __launch_bounds__(256) attn_kernel(
    const float* __restrict__ kqv_dt,   // dst-type kqv rows (q at +256)
    const float* __restrict__ ke, const float* __restrict__ ve,
    const int* __restrict__ off, const int* __restrict__ srt,
    const float* __restrict__ p, float* __restrict__ agg)
{
    int w = (blockIdx.x * 256 + threadIdx.x) >> 5;
    if (w >= NN) return;
    const int lane = threadIdx.x & 31;
    const int h = lane >> 2;
    const int dq = (lane & 3) * 8;
    const int co = h * 32 + dq;

    const float* qr = kqv_dt + (size_t)w * 768 + 256 + co;
    float4 q0 = *(const float4*)qr;
    float4 q1 = *(const float4*)(qr + 4);
    const float ph = p[h] * 0.17677669529663688110f;   // 1/sqrt(32)

    float m = -INFINITY, z = 0.0f;
    float4 a0 = {0.f, 0.f, 0.f, 0.f};
    float4 a1 = {0.f, 0.f, 0.f, 0.f};

    const int b = off[w], e2 = off[w + 1];
    for (int j = b; j < e2; j++) {
        int s = srt[j];
        const float* kr = ke + (size_t)s * 256 + co;
        const float* vr = ve + (size_t)s * 256 + co;
        float4 k0 = *(const float4*)kr;
        float4 k1 = *(const float4*)(kr + 4);
        float4 v0 = *(const float4*)vr;
        float4 v1 = *(const float4*)(vr + 4);

        float dot = q0.x * k0.x + q0.y * k0.y + q0.z * k0.z + q0.w * k0.w
                  + q1.x * k1.x + q1.y * k1.y + q1.z * k1.z + q1.w * k1.w;
        dot += __shfl_xor_sync(0xffffffffu, dot, 1);
        dot += __shfl_xor_sync(0xffffffffu, dot, 2);
        float sc = dot * ph;

        float nm = fmaxf(m, sc);
        float scale = __expf(m - nm);      // first iter: exp(-inf) = 0
        float ea = __expf(sc - nm);
        z = z * scale + ea;
        a0.x = a0.x * scale + ea * v0.x;  a0.y = a0.y * scale + ea * v0.y;
        a0.z = a0.z * scale + ea * v0.z;  a0.w = a0.w * scale + ea * v0.w;
        a1.x = a1.x * scale + ea * v1.x;  a1.y = a1.y * scale + ea * v1.y;
        a1.z = a1.z * scale + ea * v1.z;  a1.w = a1.w * scale + ea * v1.w;
        m = nm;
    }

    float inv = (z > 0.0f) ? 1.0f / z : 0.0f;
    float* ar = agg + (size_t)w * 256 + co;
    float4 o0 = {a0.x * inv, a0.y * inv, a0.z * inv, a0.w * inv};
    float4 o1 = {a1.x * inv, a1.y * inv, a1.z * inv, a1.w * inv};
    *(float4*)ar = o0;
    *(float4*)(ar + 4) = o1;
}

// ---------------- driver ----------------
extern "C" void kernel_launch(void* const* d_in, const int* in_sizes, int n_in,
                              void* d_out, int out_size)
{
    const float* x0 = (const float*)d_in[0];
    const float* x1 = (const float*)d_in[1];
    const int*   e_dr = (const int*)d_in[2];   // [2,E] row0=src(drug) row1=dst(react)
    const int*   e_rd = (const int*)d_in[3];
    const float* Wk = (const float*)d_in[4];   // [L,2,F,3F]
    const float* bk = (const float*)d_in[5];   // [L,2,3F]
    const float* Ar = (const float*)d_in[6];   // [L,2,H,D,D]
    const float* Mr = (const float*)d_in[7];
    const float* pr = (const float*)d_in[8];   // [L,2,H]
    const float* Wo = (const float*)d_in[9];   // [L,2,F,F]
    const float* bo = (const float*)d_in[10];  // [L,2,F]
    const float* sk = (const float*)d_in[11];  // [L,2]
    float* out = (float*)d_out;

    float *gx, *gkqv, *gke, *gve, *gagg;
    int *goff, *gsrt;
    cudaGetSymbolAddress((void**)&gx,   g_x);
    cudaGetSymbolAddress((void**)&gkqv, g_kqv);
    cudaGetSymbolAddress((void**)&gke,  g_ke);
    cudaGetSymbolAddress((void**)&gve,  g_ve);
    cudaGetSymbolAddress((void**)&gagg, g_agg);
    cudaGetSymbolAddress((void**)&goff, g_off);
    cudaGetSymbolAddress((void**)&gsrt, g_srt);

    const int copyBlocks = (NN * FF + 255) / 256;
    copy_in_kernel<<<copyBlocks, 256>>>(x0, x1);

    // ---- CSR build (once per call; edges identical across layers) ----
    csr_zero_kernel<<<(2 * NP + 255) / 256, 256>>>();
    csr_hist_kernel<<<(EE + 255) / 256, 256>>>(e_dr + EE, e_rd + EE);
    csr_scan_kernel<<<2, 1024>>>();
    csr_scatter_kernel<<<(EE + 255) / 256, 256>>>(e_dr + EE, e_rd + EE);
    csr_sort_kernel<<<(2 * NP + 255) / 256, 256>>>(e_dr, e_rd);

    for (int l = 0; l < LL; l++) {
        // kqv = x @ Wk + bk
        for (int t = 0; t < 2; t++) {
            gemm_kernel<false, false><<<dim3(768 / 128, NP / 128), 256>>>(
                gx + (size_t)t * NP * FF,
                Wk + ((size_t)(l * 2 + t)) * FF * 3 * FF,
                bk + (size_t)(l * 2 + t) * 3 * FF,
                gkqv + (size_t)t * NP * 3 * FF,
                FF, 3 * FF, nullptr, nullptr);
        }

        // relation transforms: et=0: src type 0; et=1: src type 1
        for (int et = 0; et < 2; et++) {
            int st = et;
            const float* kqv_st = gkqv + (size_t)st * NP * 3 * FF;
            rel_kernel<<<NP / 16, 256>>>(kqv_st,       Ar + (size_t)(l * 2 + et) * HH * DD * DD,
                                         gke + (size_t)et * NP * FF);
            rel_kernel<<<NP / 16, 256>>>(kqv_st + 512, Mr + (size_t)(l * 2 + et) * HH * DD * DD,
                                         gve + (size_t)et * NP * FF);
        }

        // fused edge attention (CSR, online softmax, no atomics)
        for (int et = 0; et < 2; et++) {
            int dt = 1 - et;
            attn_kernel<<<(NN * 32 + 255) / 256, 256>>>(
                gkqv + (size_t)dt * NP * 3 * FF,
                gke + (size_t)et * NP * FF,
                gve + (size_t)et * NP * FF,
                goff + (size_t)et * (NP + 1),
                gsrt + (size_t)et * EE,
                pr + (size_t)(l * 2 + et) * HH,
                gagg + (size_t)dt * NP * FF);
        }

        // out = relu( a*(gelu(agg) @ Wo + bo) + (1-a)*x )   (in place on x)
        for (int t = 0; t < 2; t++) {
            gemm_kernel<true, true><<<dim3(FF / 128, NP / 128), 256>>>(
                gagg + (size_t)t * NP * FF,
                Wo + (size_t)(l * 2 + t) * FF * FF,
                bo + (size_t)(l * 2 + t) * FF,
                gx + (size_t)t * NP * FF,
                FF, FF,
                gx + (size_t)t * NP * FF,
                sk + (l * 2 + t));
        }
    }

    copy_out_kernel<<<copyBlocks, 256>>>(out);
}

// round 6
// speedup vs baseline: 1.6042x; 1.3325x over previous
#include <cuda_runtime.h>
#include <math.h>

#define NN 30000
#define NP 30080          // 235 * 128, padded rows are zero / never referenced by edges
#define EE 200000
#define FF 256
#define HH 8
#define DD 32
#define LL 3

typedef unsigned long long u64;

// ---------------- scratch (static device memory; no allocation) ----------------
__device__ float g_x  [2 * (size_t)NP * FF];        // node features, both types
__device__ float g_kqv[2 * (size_t)NP * 3 * FF];    // [type][node][768] = ke | q | ve (post-fold)
__device__ float g_agg[2 * (size_t)NP * FF];        // per dst-type aggregation (padded rows stay 0)
__device__ float g_We [6 * (size_t)FF * 3 * FF];    // folded W_kqv: [l*2+t][256][768]
__device__ float g_be [6 * 3 * FF];                 // folded bias

// CSR scratch (built once per call; edges identical across layers)
__device__ int g_deg[2 * NP];
__device__ int g_cur[2 * NP];
__device__ int g_off[2 * (NP + 1)];
__device__ int g_eid[2 * EE];
__device__ int g_srt[2 * EE];

__device__ __forceinline__ float gelu_exact(float x) {
    return 0.5f * x * (1.0f + erff(x * 0.70710678118654752440f));
}

__device__ __forceinline__ void ffma2(u64& d, u64 a, u64 b) {
    asm("fma.rn.f32x2 %0, %1, %2, %0;" : "+l"(d) : "l"(a), "l"(b));
}
__device__ __forceinline__ u64 dupf(float x) {
    u64 r; asm("mov.b64 %0, {%1, %1};" : "=l"(r) : "f"(x)); return r;
}

// ---------------- copies ----------------
__global__ void copy_in_kernel(const float* __restrict__ x0, const float* __restrict__ x1) {
    size_t i = (size_t)blockIdx.x * 256 + threadIdx.x;
    if (i < (size_t)NN * FF) {
        g_x[i] = x0[i];
        g_x[(size_t)NP * FF + i] = x1[i];
    }
}

__global__ void copy_out_kernel(float* __restrict__ out) {
    size_t i = (size_t)blockIdx.x * 256 + threadIdx.x;
    if (i < (size_t)NN * FF) {
        out[i] = g_x[i];
        out[(size_t)NN * FF + i] = g_x[(size_t)NP * FF + i];
    }
}

// ---------------- fold relation transforms into W_kqv ----------------
// blockIdx.x in [0,96): lt = bx>>4, part = (bx>>3)&1 (0:k/A, 1:v/M), h = bx&7
__global__ void __launch_bounds__(256) fold_kernel(
    const float* __restrict__ Wk, const float* __restrict__ bk,
    const float* __restrict__ Ar, const float* __restrict__ Mr)
{
    int bx = blockIdx.x;
    int lt = bx >> 4;
    int part = (bx >> 3) & 1;
    int h = bx & 7;
    const float* A = (part ? Mr : Ar) + (size_t)lt * HH * DD * DD + h * DD * DD;
    __shared__ float sA[DD * DD];
    int tid = threadIdx.x;
    for (int i = tid; i < DD * DD; i += 256) sA[i] = A[i];
    __syncthreads();
    int e = tid & 31;
    int rg = tid >> 5;
    int col = (part ? 512 : 0) + h * 32;   // src cols == dst cols
    for (int r = rg * 32; r < rg * 32 + 32; r++) {
        const float* w = Wk + (size_t)lt * 256 * 768 + (size_t)r * 768 + col;
        float acc = 0.0f;
#pragma unroll
        for (int d = 0; d < 32; d++) acc = fmaf(w[d], sA[d * 32 + e], acc);
        g_We[(size_t)lt * 256 * 768 + (size_t)r * 768 + col + e] = acc;
    }
    if (rg == 0) {
        const float* b = bk + (size_t)lt * 768 + col;
        float acc = 0.0f;
#pragma unroll
        for (int d = 0; d < 32; d++) acc = fmaf(b[d], sA[d * 32 + e], acc);
        g_be[lt * 768 + col + e] = acc;
    }
}

__global__ void foldq_kernel(const float* __restrict__ Wk, const float* __restrict__ bk) {
    int idx = blockIdx.x * 256 + threadIdx.x;
    if (idx < 6 * 256 * 256) {
        int lt = idx >> 16;
        int rem = idx & 65535;
        int r = rem >> 8;
        int c = rem & 255;
        size_t o = (size_t)lt * 256 * 768 + (size_t)r * 768 + 256 + c;
        g_We[o] = Wk[o];
    }
    if (idx < 6 * 256) {
        int lt = idx >> 8, c = idx & 255;
        g_be[lt * 768 + 256 + c] = bk[lt * 768 + 256 + c];
    }
}

// ---------------- CSR build ----------------
__global__ void csr_zero_kernel() {
    int i = blockIdx.x * 256 + threadIdx.x;
    if (i < 2 * NP) { g_deg[i] = 0; g_cur[i] = 0; }
}

__global__ void csr_hist_kernel(const int* __restrict__ dst0, const int* __restrict__ dst1) {
    int e = blockIdx.x * 256 + threadIdx.x;
    if (e < EE) {
        atomicAdd(&g_deg[dst0[e]], 1);
        atomicAdd(&g_deg[NP + dst1[e]], 1);
    }
}

// exclusive scan per edge type; one block (1024 threads) per type, chunked serial + shfl scan
__global__ void __launch_bounds__(1024) csr_scan_kernel() {
    const int t = blockIdx.x;
    const int* deg = g_deg + t * NP;
    int* off = g_off + t * (NP + 1);
    const int tid = threadIdx.x;
    const int CH = 30;                      // 1024*30 = 30720 >= NP
    int base = tid * CH;
    int local[CH];
    int s = 0;
#pragma unroll
    for (int i = 0; i < CH; i++) {
        int idx = base + i;
        int v = (idx < NP) ? deg[idx] : 0;
        local[i] = s; s += v;
    }
    __shared__ int wsum[32];
    int lane = tid & 31, wid = tid >> 5;
    int ws = s;
#pragma unroll
    for (int o = 1; o < 32; o <<= 1) { int y = __shfl_up_sync(~0u, ws, o); if (lane >= o) ws += y; }
    if (lane == 31) wsum[wid] = ws;
    __syncthreads();
    if (wid == 0) {
        int v = wsum[lane];
#pragma unroll
        for (int o = 1; o < 32; o <<= 1) { int y = __shfl_up_sync(~0u, v, o); if (lane >= o) v += y; }
        wsum[lane] = v;
    }
    __syncthreads();
    int warpEx = (wid > 0) ? wsum[wid - 1] : 0;
    int ex = warpEx + ws - s;
#pragma unroll
    for (int i = 0; i < CH; i++) {
        int idx = base + i;
        if (idx < NP) off[idx] = ex + local[i];
    }
    if (tid == 1023) off[NP] = warpEx + ws;
}

__global__ void csr_scatter_kernel(const int* __restrict__ dst0, const int* __restrict__ dst1) {
    int e = blockIdx.x * 256 + threadIdx.x;
    if (e >= EE) return;
    int d0 = dst0[e];
    int p0 = g_off[d0] + atomicAdd(&g_cur[d0], 1);
    g_eid[p0] = e;
    int d1 = dst1[e];
    int p1 = g_off[(NP + 1) + d1] + atomicAdd(&g_cur[NP + d1], 1);
    g_eid[EE + p1] = e;
}

// per-dst insertion sort by edge id (determinism) + convert eid -> src
__global__ void csr_sort_kernel(const int* __restrict__ s0, const int* __restrict__ s1) {
    int idx = blockIdx.x * 256 + threadIdx.x;
    if (idx >= 2 * NP) return;
    int t = (idx >= NP) ? 1 : 0;
    int d = idx - t * NP;
    const int* off = g_off + t * (NP + 1);
    int b = off[d], e = off[d + 1];
    int* a = g_eid + t * EE;
    for (int i = b + 1; i < e; i++) {
        int key = a[i];
        int j = i - 1;
        while (j >= b && a[j] > key) { a[j + 1] = a[j]; j--; }
        a[j + 1] = key;
    }
    const int* sarr = t ? s1 : s0;
    int* o = g_srt + t * EE;
    for (int i = b; i < e; i++) o[i] = sarr[a[i]];
}

// ---------------- SGEMM (f32x2 packed FMA): C = op(A)@B + bias (+ epilogue) ----------------
// BM=BN=128, BK=8, 256 threads, 8x8 per thread (as 8x4 f32x2 pairs). grid.z batches node type.
template <bool GELU_A, bool EPI>
__global__ void __launch_bounds__(256) gemm_kernel(
    const float* __restrict__ A, const float* __restrict__ B,
    const float* __restrict__ bias, float* __restrict__ C,
    int K, int Nc,
    size_t sA_, size_t sB_, size_t sb_, size_t sC_,
    const float* __restrict__ xres, const float* __restrict__ skp)
{
    const int z = blockIdx.z;
    A += (size_t)z * sA_; B += (size_t)z * sB_; bias += (size_t)z * sb_; C += (size_t)z * sC_;
    if (EPI) { xres += (size_t)z * sA_; skp += z; }

    __shared__ float As[8][128];
    __shared__ float Bs[8][128];
    const int tid = threadIdx.x;
    const int m0 = blockIdx.y * 128;
    const int n0 = blockIdx.x * 128;
    const int tx = tid & 15;
    const int ty = tid >> 4;

    u64 acc2[8][4];
#pragma unroll
    for (int i = 0; i < 8; i++)
#pragma unroll
        for (int j = 0; j < 4; j++) acc2[i][j] = 0ULL;

    const int aRow = tid >> 1;
    const int aK   = (tid & 1) * 4;
    const int bRow = tid >> 5;
    const int bCol = (tid & 31) * 4;
    const float* Ap = A + (size_t)(m0 + aRow) * K + aK;
    const float* Bp = B + (size_t)bRow * Nc + n0 + bCol;

    for (int k0 = 0; k0 < K; k0 += 8) {
        float4 av = *(const float4*)(Ap + k0);
        float4 bv = *(const float4*)(Bp + (size_t)k0 * Nc);
        if (GELU_A) {
            av.x = gelu_exact(av.x); av.y = gelu_exact(av.y);
            av.z = gelu_exact(av.z); av.w = gelu_exact(av.w);
        }
        __syncthreads();
        As[aK + 0][aRow] = av.x; As[aK + 1][aRow] = av.y;
        As[aK + 2][aRow] = av.z; As[aK + 3][aRow] = av.w;
        *(float4*)&Bs[bRow][bCol] = bv;
        __syncthreads();
#pragma unroll
        for (int k = 0; k < 8; k++) {
            float4 a0 = *(const float4*)&As[k][ty * 8];
            float4 a1 = *(const float4*)&As[k][ty * 8 + 4];
            const u64* bp = (const u64*)&Bs[k][tx * 8];
            u64 br0 = bp[0], br1 = bp[1], br2 = bp[2], br3 = bp[3];
            u64 ad[8];
            ad[0] = dupf(a0.x); ad[1] = dupf(a0.y); ad[2] = dupf(a0.z); ad[3] = dupf(a0.w);
            ad[4] = dupf(a1.x); ad[5] = dupf(a1.y); ad[6] = dupf(a1.z); ad[7] = dupf(a1.w);
#pragma unroll
            for (int i = 0; i < 8; i++) {
                ffma2(acc2[i][0], ad[i], br0);
                ffma2(acc2[i][1], ad[i], br1);
                ffma2(acc2[i][2], ad[i], br2);
                ffma2(acc2[i][3], ad[i], br3);
            }
        }
    }

    float sAv = 0.0f;
    if (EPI) sAv = 1.0f / (1.0f + __expf(-skp[0]));
#pragma unroll
    for (int i = 0; i < 8; i++) {
        int m = m0 + ty * 8 + i;
#pragma unroll
        for (int j = 0; j < 4; j++) {
            float2 v = *(float2*)&acc2[i][j];
            int n = n0 + tx * 8 + 2 * j;
            float o0 = v.x + bias[n];
            float o1 = v.y + bias[n + 1];
            if (EPI) {
                o0 = sAv * o0 + (1.0f - sAv) * xres[(size_t)m * FF + n];
                o1 = sAv * o1 + (1.0f - sAv) * xres[(size_t)m * FF + n + 1];
                o0 = fmaxf(o0, 0.0f);
                o1 = fmaxf(o1, 0.0f);
            }
            C[(size_t)m * Nc + n] = o0;
            C[(size_t)m * Nc + n + 1] = o1;
        }
    }
}

// ---------------- fused edge attention: one warp per (dst type, dst node) ----------------
// kqv row layout: [ ke(256) | q(256) | ve(256) ]. lane: h = lane>>2, 8-float slice = (lane&3)*8
__global__ void __launch_bounds__(256) attn_kernel(const float* __restrict__ pr_l)
{
    int w = (blockIdx.x * 256 + threadIdx.x) >> 5;
    if (w >= 2 * NN) return;
    const int dt = (w >= NN) ? 1 : 0;
    const int node = w - dt * NN;
    const int et = 1 - dt;          // edge type whose dst is dt; src type == et
    const float* kqv_d = g_kqv + (size_t)dt * NP * 768;
    const float* kqv_s = g_kqv + (size_t)et * NP * 768;
    const int* off = g_off + et * (NP + 1);
    const int* srt = g_srt + et * EE;
    float* agg = g_agg + (size_t)dt * NP * FF;

    const int lane = threadIdx.x & 31;
    const int h = lane >> 2;
    const int co = h * 32 + (lane & 3) * 8;

    const float* qr = kqv_d + (size_t)node * 768 + 256 + co;
    float4 q0 = *(const float4*)qr;
    float4 q1 = *(const float4*)(qr + 4);
    const float ph = pr_l[et * HH + h] * 0.17677669529663688110f;   // 1/sqrt(32)

    float m = -INFINITY, z = 0.0f;
    float4 a0 = {0.f, 0.f, 0.f, 0.f};
    float4 a1 = {0.f, 0.f, 0.f, 0.f};

    const int b = off[node], e2 = off[node + 1];
    for (int j = b; j < e2; j++) {
        int s = srt[j];
        const float* kr = kqv_s + (size_t)s * 768 + co;          // ke at +0
        const float* vr = kr + 512;                               // ve at +512
        float4 k0 = *(const float4*)kr;
        float4 k1 = *(const float4*)(kr + 4);
        float4 v0 = *(const float4*)vr;
        float4 v1 = *(const float4*)(vr + 4);

        float dot = q0.x * k0.x + q0.y * k0.y + q0.z * k0.z + q0.w * k0.w
                  + q1.x * k1.x + q1.y * k1.y + q1.z * k1.z + q1.w * k1.w;
        dot += __shfl_xor_sync(0xffffffffu, dot, 1);
        dot += __shfl_xor_sync(0xffffffffu, dot, 2);
        float sc = dot * ph;

        float nm = fmaxf(m, sc);
        float scale = __expf(m - nm);      // first iter: exp(-inf) = 0
        float ea = __expf(sc - nm);
        z = z * scale + ea;
        a0.x = a0.x * scale + ea * v0.x;  a0.y = a0.y * scale + ea * v0.y;
        a0.z = a0.z * scale + ea * v0.z;  a0.w = a0.w * scale + ea * v0.w;
        a1.x = a1.x * scale + ea * v1.x;  a1.y = a1.y * scale + ea * v1.y;
        a1.z = a1.z * scale + ea * v1.z;  a1.w = a1.w * scale + ea * v1.w;
        m = nm;
    }

    float inv = (z > 0.0f) ? 1.0f / z : 0.0f;
    float* ar = agg + (size_t)node * 256 + co;
    float4 o0 = {a0.x * inv, a0.y * inv, a0.z * inv, a0.w * inv};
    float4 o1 = {a1.x * inv, a1.y * inv, a1.z * inv, a1.w * inv};
    *(float4*)ar = o0;
    *(float4*)(ar + 4) = o1;
}

// ---------------- driver ----------------
extern "C" void kernel_launch(void* const* d_in, const int* in_sizes, int n_in,
                              void* d_out, int out_size)
{
    const float* x0 = (const float*)d_in[0];
    const float* x1 = (const float*)d_in[1];
    const int*   e_dr = (const int*)d_in[2];   // [2,E] row0=src(drug) row1=dst(react)
    const int*   e_rd = (const int*)d_in[3];
    const float* Wk = (const float*)d_in[4];   // [L,2,F,3F]
    const float* bk = (const float*)d_in[5];   // [L,2,3F]
    const float* Ar = (const float*)d_in[6];   // [L,2,H,D,D]
    const float* Mr = (const float*)d_in[7];
    const float* pr = (const float*)d_in[8];   // [L,2,H]
    const float* Wo = (const float*)d_in[9];   // [L,2,F,F]
    const float* bo = (const float*)d_in[10];  // [L,2,F]
    const float* sk = (const float*)d_in[11];  // [L,2]
    float* out = (float*)d_out;

    float *gx, *gkqv, *gagg, *gWe, *gbe;
    cudaGetSymbolAddress((void**)&gx,   g_x);
    cudaGetSymbolAddress((void**)&gkqv, g_kqv);
    cudaGetSymbolAddress((void**)&gagg, g_agg);
    cudaGetSymbolAddress((void**)&gWe,  g_We);
    cudaGetSymbolAddress((void**)&gbe,  g_be);

    const int copyBlocks = (NN * FF + 255) / 256;
    copy_in_kernel<<<copyBlocks, 256>>>(x0, x1);

    // ---- fold relation transforms into kqv weights (once per call) ----
    fold_kernel<<<96, 256>>>(Wk, bk, Ar, Mr);
    foldq_kernel<<<(6 * 256 * 256 + 255) / 256, 256>>>(Wk, bk);

    // ---- CSR build (once per call; edges identical across layers) ----
    csr_zero_kernel<<<(2 * NP + 255) / 256, 256>>>();
    csr_hist_kernel<<<(EE + 255) / 256, 256>>>(e_dr + EE, e_rd + EE);
    csr_scan_kernel<<<2, 1024>>>();
    csr_scatter_kernel<<<(EE + 255) / 256, 256>>>(e_dr + EE, e_rd + EE);
    csr_sort_kernel<<<(2 * NP + 255) / 256, 256>>>(e_dr, e_rd);

    for (int l = 0; l < LL; l++) {
        // kqv = x @ W_eff + b_eff  (produces ke|q|ve directly; both types via grid.z)
        gemm_kernel<false, false><<<dim3(768 / 128, NP / 128, 2), 256>>>(
            gx, gWe + (size_t)l * 2 * 256 * 768, gbe + (size_t)l * 2 * 768, gkqv,
            FF, 3 * FF,
            (size_t)NP * FF, (size_t)256 * 768, (size_t)768, (size_t)NP * 768,
            nullptr, nullptr);

        // fused edge attention (both edge types, CSR, online softmax, no atomics)
        attn_kernel<<<(2 * NN * 32 + 255) / 256, 256>>>(pr + (size_t)l * 2 * HH);

        // out = relu( a*(gelu(agg) @ Wo + bo) + (1-a)*x )   (in place on x, both types)
        gemm_kernel<true, true><<<dim3(FF / 128, NP / 128, 2), 256>>>(
            gagg, Wo + (size_t)l * 2 * FF * FF, bo + (size_t)l * 2 * FF, gx,
            FF, FF,
            (size_t)NP * FF, (size_t)FF * FF, (size_t)FF, (size_t)NP * FF,
            gx, sk + l * 2);
    }

    copy_out_kernel<<<copyBlocks, 256>>>(out);
}

// round 10
// speedup vs baseline: 3.0885x; 1.9252x over previous
#include <cuda_runtime.h>
#include <math.h>
#include <stdint.h>

#define NN 30000
#define NP 30080          // 235 * 128
#define EE 200000
#define FF 256
#define HH 8
#define DD 32
#define LL 3

typedef unsigned long long u64;

// tcgen05 path only on arch-specific ('a') compilation passes; generic compute_103
// passes get the FFMA2 fallback so ptxas never sees tcgen05 on a non-'a' target.
#if defined(__CUDA_ARCH__) && (defined(__CUDA_ARCH_FEAT_SM103_ALL) || defined(__CUDA_ARCH_FEAT_SM100_ALL) || defined(__CUDA_ARCH_SPECIFIC__))
#define TC_PATH 1
#else
#define TC_PATH 0
#endif

// ---------------- scratch (static device memory; no allocation) ----------------
__device__ float g_x  [2 * (size_t)NP * FF];
__device__ float g_kqv[2 * (size_t)NP * 3 * FF];    // ke | q | ve
__device__ float g_agg[2 * (size_t)NP * FF];        // padded rows stay 0 forever
__device__ float g_WeT[6 * (size_t)768 * 256];      // folded W_kqv, transposed: [lt][n][k]
__device__ float g_WoT[6 * (size_t)256 * 256];      // W_out transposed: [lt][n][k]
__device__ float g_be [6 * 3 * FF];

__device__ int g_deg[2 * NP];
__device__ int g_cur[2 * NP];
__device__ int g_off[2 * (NP + 1)];
__device__ int g_eid[2 * EE];
__device__ int g_srt[2 * EE];

__device__ __forceinline__ float gelu_exact(float x) {
    return 0.5f * x * (1.0f + erff(x * 0.70710678118654752440f));
}
__device__ __forceinline__ void ffma2(u64& d, u64 a, u64 b) {
    asm("fma.rn.f32x2 %0, %1, %2, %0;" : "+l"(d) : "l"(a), "l"(b));
}
__device__ __forceinline__ u64 dupf(float x) {
    u64 r; asm("mov.b64 %0, {%1, %1};" : "=l"(r) : "f"(x)); return r;
}
__device__ __forceinline__ uint32_t smem_u32(const void* p) {
    uint32_t a;
    asm("{ .reg .u64 t; cvta.to.shared.u64 t, %1; cvt.u32.u64 %0, t; }" : "=r"(a) : "l"(p));
    return a;
}

#if TC_PATH
// ---------------- tcgen05 helpers (compiled only on 'a' targets) ----------------
__device__ __forceinline__ uint32_t swz(uint32_t b) { return b ^ ((b >> 3) & 0x70u); }
__device__ __forceinline__ uint32_t tf32hi(float v) {
    uint32_t r; asm("cvt.rna.tf32.f32 %0, %1;" : "=r"(r) : "f"(v)); return r;
}
__device__ __forceinline__ u64 mkdesc(uint32_t addr) {
    const u64 base = (2ULL << 61) | (1ULL << 46) | (64ULL << 32) | (1ULL << 16);  // SW128, v1, SBO=64, LBO=1
    return base | ((u64)(addr >> 4) & 0x3FFFULL);
}
// idesc kind::tf32: dF32(1<<4) | aTF32(2<<7) | bTF32(2<<10) | N128(16<<17) | M128(8<<24)
#define IDESC_TF32 0x8200910u

__device__ __forceinline__ void mma_tf32(uint32_t d, u64 ad, u64 bd, uint32_t en) {
    asm volatile(
        "{\n\t.reg .pred p;\n\t"
        "setp.ne.u32 p, %4, 0;\n\t"
        "tcgen05.mma.cta_group::1.kind::tf32 [%0], %1, %2, %3, {%5, %5, %5, %5}, p;\n\t"
        "}"
        :: "r"(d), "l"(ad), "l"(bd), "r"(IDESC_TF32), "r"(en), "r"(0u)
        : "memory");
}
__device__ __forceinline__ void tmem_alloc(uint32_t dst_smem, uint32_t ncols) {
    asm volatile("tcgen05.alloc.cta_group::1.sync.aligned.shared::cta.b32 [%0], %1;"
                 :: "r"(dst_smem), "r"(ncols) : "memory");
}
__device__ __forceinline__ void tmem_relinq() {
    asm volatile("tcgen05.relinquish_alloc_permit.cta_group::1.sync.aligned;");
}
__device__ __forceinline__ void tmem_dealloc(uint32_t base, uint32_t ncols) {
    asm volatile("tcgen05.dealloc.cta_group::1.sync.aligned.b32 %0, %1;" :: "r"(base), "r"(ncols));
}
__device__ __forceinline__ void mbar_init(uint32_t mbar, uint32_t cnt) {
    asm volatile("mbarrier.init.shared.b64 [%0], %1;" :: "r"(mbar), "r"(cnt) : "memory");
}
__device__ __forceinline__ void tc_commit(uint32_t mbar) {
    asm volatile("tcgen05.commit.cta_group::1.mbarrier::arrive::one.shared::cluster.b64 [%0];"
                 :: "r"(mbar) : "memory");
}
__device__ __forceinline__ void mbar_wait(uint32_t mbar, uint32_t parity) {
    uint32_t done = 0;
    do {
        asm volatile(
            "{\n\t.reg .pred p;\n\t"
            "mbarrier.try_wait.parity.acquire.cta.shared::cta.b64 p, [%1], %2, 0x989680;\n\t"
            "selp.b32 %0, 1, 0, p;\n\t}"
            : "=r"(done) : "r"(mbar), "r"(parity) : "memory");
    } while (!done);
}
__device__ __forceinline__ void fence_async_smem() {
    asm volatile("fence.proxy.async.shared::cta;" ::: "memory");
}
__device__ __forceinline__ void tc_fence_after() {
    asm volatile("tcgen05.fence::after_thread_sync;" ::: "memory");
}
__device__ __forceinline__ void tc_fence_before() {
    asm volatile("tcgen05.fence::before_thread_sync;" ::: "memory");
}
__device__ __forceinline__ void tc_wait_ld() {
    asm volatile("tcgen05.wait::ld.sync.aligned;" ::: "memory");
}
__device__ __forceinline__ void ldtm32(uint32_t (&r)[32], uint32_t tmem_addr) {
    asm volatile(
        "tcgen05.ld.sync.aligned.32x32b.x32.b32 "
        "{%0, %1, %2, %3, %4, %5, %6, %7, "
        " %8, %9, %10, %11, %12, %13, %14, %15, "
        " %16, %17, %18, %19, %20, %21, %22, %23, "
        " %24, %25, %26, %27, %28, %29, %30, %31}, [%32];"
        : "=r"(r[0]),  "=r"(r[1]),  "=r"(r[2]),  "=r"(r[3]),
          "=r"(r[4]),  "=r"(r[5]),  "=r"(r[6]),  "=r"(r[7]),
          "=r"(r[8]),  "=r"(r[9]),  "=r"(r[10]), "=r"(r[11]),
          "=r"(r[12]), "=r"(r[13]), "=r"(r[14]), "=r"(r[15]),
          "=r"(r[16]), "=r"(r[17]), "=r"(r[18]), "=r"(r[19]),
          "=r"(r[20]), "=r"(r[21]), "=r"(r[22]), "=r"(r[23]),
          "=r"(r[24]), "=r"(r[25]), "=r"(r[26]), "=r"(r[27]),
          "=r"(r[28]), "=r"(r[29]), "=r"(r[30]), "=r"(r[31])
        : "r"(tmem_addr));
}

// load a [128 x 32] fp32 chunk (row stride 256) into hi/lo TF32 SW128 tiles; 256 threads
__device__ __forceinline__ void load_chunk_tile(
    const float* __restrict__ src, uint32_t dHi, uint32_t dLo, bool dogelu, int tid)
{
#pragma unroll
    for (int pass = 0; pass < 4; pass++) {
        int row = pass * 32 + (tid >> 3);
        int j4  = (tid & 7) * 4;
        float4 v = *(const float4*)(src + (size_t)row * 256 + j4);
        if (dogelu) {
            v.x = gelu_exact(v.x); v.y = gelu_exact(v.y);
            v.z = gelu_exact(v.z); v.w = gelu_exact(v.w);
        }
        uint32_t h0 = tf32hi(v.x), h1 = tf32hi(v.y), h2 = tf32hi(v.z), h3 = tf32hi(v.w);
        float l0 = v.x - __uint_as_float(h0);
        float l1 = v.y - __uint_as_float(h1);
        float l2 = v.z - __uint_as_float(h2);
        float l3 = v.w - __uint_as_float(h3);
        uint32_t boff = (uint32_t)(row >> 3) * 1024u + (uint32_t)(row & 7) * 128u + (uint32_t)j4 * 4u;
        uint32_t sw = swz(boff);
        asm volatile("st.shared.v4.b32 [%0], {%1,%2,%3,%4};"
                     :: "r"(dHi + sw), "r"(h0), "r"(h1), "r"(h2), "r"(h3) : "memory");
        asm volatile("st.shared.v4.b32 [%0], {%1,%2,%3,%4};"
                     :: "r"(dLo + sw), "r"(__float_as_uint(l0)), "r"(__float_as_uint(l1)),
                        "r"(__float_as_uint(l2)), "r"(__float_as_uint(l3)) : "memory");
    }
}
#endif  // TC_PATH

// ---------------- copies ----------------
__global__ void copy_in_kernel(const float* __restrict__ x0, const float* __restrict__ x1) {
    size_t i = (size_t)blockIdx.x * 256 + threadIdx.x;
    if (i < (size_t)NN * FF) {
        g_x[i] = x0[i];
        g_x[(size_t)NP * FF + i] = x1[i];
    }
}
__global__ void copy_out_kernel(float* __restrict__ out) {
    size_t i = (size_t)blockIdx.x * 256 + threadIdx.x;
    if (i < (size_t)NN * FF) {
        out[i] = g_x[i];
        out[(size_t)NN * FF + i] = g_x[(size_t)NP * FF + i];
    }
}

// ---------------- fold relation transforms into W_kqv (transposed output) ----------------
__global__ void __launch_bounds__(256) fold_kernel(
    const float* __restrict__ Wk, const float* __restrict__ bk,
    const float* __restrict__ Ar, const float* __restrict__ Mr)
{
    int bx = blockIdx.x;
    int lt = bx >> 4;
    int part = (bx >> 3) & 1;
    int h = bx & 7;
    const float* A = (part ? Mr : Ar) + (size_t)lt * HH * DD * DD + h * DD * DD;
    __shared__ float sA[DD * DD];
    int tid = threadIdx.x;
    for (int i = tid; i < DD * DD; i += 256) sA[i] = A[i];
    __syncthreads();
    int e = tid & 31;
    int rg = tid >> 5;
    int col = (part ? 512 : 0) + h * 32;
    for (int r = rg * 32; r < rg * 32 + 32; r++) {
        const float* w = Wk + (size_t)lt * 256 * 768 + (size_t)r * 768 + col;
        float acc = 0.0f;
#pragma unroll
        for (int d = 0; d < 32; d++) acc = fmaf(w[d], sA[d * 32 + e], acc);
        g_WeT[(size_t)lt * 768 * 256 + (size_t)(col + e) * 256 + r] = acc;
    }
    if (rg == 0) {
        const float* b = bk + (size_t)lt * 768 + col;
        float acc = 0.0f;
#pragma unroll
        for (int d = 0; d < 32; d++) acc = fmaf(b[d], sA[d * 32 + e], acc);
        g_be[lt * 768 + col + e] = acc;
    }
}

__global__ void foldq_kernel(const float* __restrict__ Wk, const float* __restrict__ bk,
                             const float* __restrict__ Wo) {
    int idx = blockIdx.x * 256 + threadIdx.x;
    if (idx < 6 * 256 * 256) {
        int lt = idx >> 16;
        int rem = idx & 65535;
        int c = rem >> 8;
        int r = rem & 255;
        g_WeT[(size_t)lt * 768 * 256 + (size_t)(256 + c) * 256 + r] =
            Wk[(size_t)lt * 256 * 768 + (size_t)r * 768 + 256 + c];
    } else if (idx < 2 * 6 * 256 * 256) {
        int i2 = idx - 6 * 256 * 256;
        int lt = i2 >> 16;
        int rem = i2 & 65535;
        int n = rem >> 8;
        int k = rem & 255;
        g_WoT[(size_t)lt * 65536 + (size_t)n * 256 + k] =
            Wo[(size_t)lt * 65536 + (size_t)k * 256 + n];
    }
    if (idx < 6 * 256) {
        int lt = idx >> 8, c = idx & 255;
        g_be[lt * 768 + 256 + c] = bk[lt * 768 + 256 + c];
    }
}

// ---------------- CSR build ----------------
__global__ void csr_zero_kernel() {
    int i = blockIdx.x * 256 + threadIdx.x;
    if (i < 2 * NP) { g_deg[i] = 0; g_cur[i] = 0; }
}
__global__ void csr_hist_kernel(const int* __restrict__ dst0, const int* __restrict__ dst1) {
    int e = blockIdx.x * 256 + threadIdx.x;
    if (e < EE) {
        atomicAdd(&g_deg[dst0[e]], 1);
        atomicAdd(&g_deg[NP + dst1[e]], 1);
    }
}
__global__ void __launch_bounds__(1024) csr_scan_kernel() {
    const int t = blockIdx.x;
    const int* deg = g_deg + t * NP;
    int* off = g_off + t * (NP + 1);
    const int tid = threadIdx.x;
    const int CH = 30;
    int base = tid * CH;
    int local[CH];
    int s = 0;
#pragma unroll
    for (int i = 0; i < CH; i++) {
        int idx = base + i;
        int v = (idx < NP) ? deg[idx] : 0;
        local[i] = s; s += v;
    }
    __shared__ int wsum[32];
    int lane = tid & 31, wid = tid >> 5;
    int ws = s;
#pragma unroll
    for (int o = 1; o < 32; o <<= 1) { int y = __shfl_up_sync(~0u, ws, o); if (lane >= o) ws += y; }
    if (lane == 31) wsum[wid] = ws;
    __syncthreads();
    if (wid == 0) {
        int v = wsum[lane];
#pragma unroll
        for (int o = 1; o < 32; o <<= 1) { int y = __shfl_up_sync(~0u, v, o); if (lane >= o) v += y; }
        wsum[lane] = v;
    }
    __syncthreads();
    int warpEx = (wid > 0) ? wsum[wid - 1] : 0;
    int ex = warpEx + ws - s;
#pragma unroll
    for (int i = 0; i < CH; i++) {
        int idx = base + i;
        if (idx < NP) off[idx] = ex + local[i];
    }
    if (tid == 1023) off[NP] = warpEx + ws;
}
__global__ void csr_scatter_kernel(const int* __restrict__ dst0, const int* __restrict__ dst1) {
    int e = blockIdx.x * 256 + threadIdx.x;
    if (e >= EE) return;
    int d0 = dst0[e];
    int p0 = g_off[d0] + atomicAdd(&g_cur[d0], 1);
    g_eid[p0] = e;
    int d1 = dst1[e];
    int p1 = g_off[(NP + 1) + d1] + atomicAdd(&g_cur[NP + d1], 1);
    g_eid[EE + p1] = e;
}
__global__ void csr_sort_kernel(const int* __restrict__ s0, const int* __restrict__ s1) {
    int idx = blockIdx.x * 256 + threadIdx.x;
    if (idx >= 2 * NP) return;
    int t = (idx >= NP) ? 1 : 0;
    int d = idx - t * NP;
    const int* off = g_off + t * (NP + 1);
    int b = off[d], e = off[d + 1];
    int* a = g_eid + t * EE;
    for (int i = b + 1; i < e; i++) {
        int key = a[i];
        int j = i - 1;
        while (j >= b && a[j] > key) { a[j + 1] = a[j]; j--; }
        a[j + 1] = key;
    }
    const int* sarr = t ? s1 : s0;
    int* o = g_srt + t * EE;
    for (int i = b; i < e; i++) o[i] = sarr[a[i]];
}

// ---------------- unified GEMM: C[M,Nc] = op(A)[M,256] @ BwT[Nc,256]^T + bias (+ epilogue) ----
// One launch config for both paths: 256 threads, 128x128 tile, SMEM_DYN dynamic smem.
// TC path: tcgen05 TF32 3x-split, K chunked by 32, single-buffer + mbarrier.
// Fallback: FFMA2 8x8-per-thread register blocking (round-6 algorithm).
#define SMEM_DYN (65536 + 1024)

template <bool GELU_A, bool EPI>
__global__ void __launch_bounds__(256) gemm_kernel(
    const float* __restrict__ A, const float* __restrict__ BwT,
    const float* __restrict__ bias, float* __restrict__ C,
    int Nc, size_t sA_, size_t sB_, size_t sb_, size_t sC_,
    const float* __restrict__ xres, const float* __restrict__ skp)
{
    const int z = blockIdx.z;
    A += (size_t)z * sA_; BwT += (size_t)z * sB_; bias += (size_t)z * sb_; C += (size_t)z * sC_;
    if (EPI) { xres += (size_t)z * sA_; skp += z; }

    extern __shared__ char dsm[];
    const int tid = threadIdx.x;
    const int m0 = blockIdx.y * 128;
    const int n0 = blockIdx.x * 128;

#if TC_PATH
    uint32_t dbase = (smem_u32(dsm) + 1023u) & ~1023u;
    const uint32_t offAhi = dbase, offAlo = dbase + 16384, offBhi = dbase + 32768, offBlo = dbase + 49152;

    __shared__ uint32_t s_tmem;
    __shared__ __align__(8) u64 s_mbar;
    const int wid = tid >> 5;
    const int lane = tid & 31;

    if (wid == 0) { tmem_alloc(smem_u32(&s_tmem), 128); tmem_relinq(); }
    if (tid == 0) mbar_init(smem_u32(&s_mbar), 1);
    __syncthreads();
    uint32_t tmem;
    asm volatile("ld.shared.b32 %0, [%1];" : "=r"(tmem) : "r"(smem_u32(&s_tmem)));
    const uint32_t mbar = smem_u32(&s_mbar);

    const float* Ap = A + (size_t)m0 * 256;
    const float* Bp = BwT + (size_t)n0 * 256;
    const u64 dAhi = mkdesc(offAhi), dAlo = mkdesc(offAlo);
    const u64 dBhi = mkdesc(offBhi), dBlo = mkdesc(offBlo);

    for (int c = 0; c < 8; c++) {
        if (c > 0) mbar_wait(mbar, (uint32_t)((c - 1) & 1));
        load_chunk_tile(Ap + c * 32, offAhi, offAlo, GELU_A, tid);
        load_chunk_tile(Bp + c * 32, offBhi, offBlo, false, tid);
        __syncthreads();
        if (tid == 0) {
            fence_async_smem();
#pragma unroll
            for (int s = 0; s < 4; s++) {
                uint32_t en = (c > 0 || s > 0) ? 1u : 0u;
                mma_tf32(tmem, dAhi + 2 * s, dBhi + 2 * s, en);
                mma_tf32(tmem, dAlo + 2 * s, dBhi + 2 * s, 1u);
                mma_tf32(tmem, dAhi + 2 * s, dBlo + 2 * s, 1u);
            }
            tc_commit(mbar);
        }
    }
    mbar_wait(mbar, 1u);   // 8th commit flips to parity-1 phase completion
    tc_fence_after();

    float sAv = 0.0f;
    if (EPI) sAv = 1.0f / (1.0f + __expf(-skp[0]));
    if (wid < 4) {                         // warpgroup 0 reads the 128 TMEM lanes
        const int m = m0 + wid * 32 + lane;
#pragma unroll
        for (int g = 0; g < 4; g++) {
            uint32_t r[32];
            ldtm32(r, tmem + g * 32);
            tc_wait_ld();
            const int nb = n0 + g * 32;
            float ov[32];
#pragma unroll
            for (int j = 0; j < 32; j++) {
                float o = __uint_as_float(r[j]) + bias[nb + j];
                if (EPI) {
                    o = sAv * o + (1.0f - sAv) * xres[(size_t)m * FF + nb + j];
                    o = fmaxf(o, 0.0f);
                }
                ov[j] = o;
            }
#pragma unroll
            for (int j = 0; j < 32; j += 4)
                *(float4*)&C[(size_t)m * Nc + nb + j] = make_float4(ov[j], ov[j+1], ov[j+2], ov[j+3]);
        }
        tc_fence_before();
    }
    __syncthreads();
    if (wid == 0) tmem_dealloc(tmem, 128);

#else   // ---------------- FFMA2 fallback (identical math, A[M,K] @ BwT[N,K]^T) ----------------
    float* As = (float*)dsm;               // [8][128]  (k-major slices of A rows)
    float* Bs = (float*)dsm + 8 * 128;     // [8][128]  (k-major slices of B rows)
    const int tx = tid & 15;
    const int ty = tid >> 4;

    u64 acc2[8][4];
#pragma unroll
    for (int i = 0; i < 8; i++)
#pragma unroll
        for (int j = 0; j < 4; j++) acc2[i][j] = 0ULL;

    const int ldRow = tid >> 1;            // 0..127
    const int ldK   = (tid & 1) * 4;       // 0 or 4
    const float* Ap = A + (size_t)(m0 + ldRow) * 256 + ldK;
    const float* Bp = BwT + (size_t)(n0 + ldRow) * 256 + ldK;

    for (int k0 = 0; k0 < 256; k0 += 8) {
        float4 av = *(const float4*)(Ap + k0);
        float4 bv = *(const float4*)(Bp + k0);
        if (GELU_A) {
            av.x = gelu_exact(av.x); av.y = gelu_exact(av.y);
            av.z = gelu_exact(av.z); av.w = gelu_exact(av.w);
        }
        __syncthreads();
        As[(ldK + 0) * 128 + ldRow] = av.x; As[(ldK + 1) * 128 + ldRow] = av.y;
        As[(ldK + 2) * 128 + ldRow] = av.z; As[(ldK + 3) * 128 + ldRow] = av.w;
        Bs[(ldK + 0) * 128 + ldRow] = bv.x; Bs[(ldK + 1) * 128 + ldRow] = bv.y;
        Bs[(ldK + 2) * 128 + ldRow] = bv.z; Bs[(ldK + 3) * 128 + ldRow] = bv.w;
        __syncthreads();
#pragma unroll
        for (int k = 0; k < 8; k++) {
            float4 a0 = *(const float4*)&As[k * 128 + ty * 8];
            float4 a1 = *(const float4*)&As[k * 128 + ty * 8 + 4];
            const u64* bp = (const u64*)&Bs[k * 128 + tx * 8];
            u64 br0 = bp[0], br1 = bp[1], br2 = bp[2], br3 = bp[3];
            u64 ad[8];
            ad[0] = dupf(a0.x); ad[1] = dupf(a0.y); ad[2] = dupf(a0.z); ad[3] = dupf(a0.w);
            ad[4] = dupf(a1.x); ad[5] = dupf(a1.y); ad[6] = dupf(a1.z); ad[7] = dupf(a1.w);
#pragma unroll
            for (int i = 0; i < 8; i++) {
                ffma2(acc2[i][0], ad[i], br0);
                ffma2(acc2[i][1], ad[i], br1);
                ffma2(acc2[i][2], ad[i], br2);
                ffma2(acc2[i][3], ad[i], br3);
            }
        }
    }

    float sAv = 0.0f;
    if (EPI) sAv = 1.0f / (1.0f + __expf(-skp[0]));
#pragma unroll
    for (int i = 0; i < 8; i++) {
        int m = m0 + ty * 8 + i;
#pragma unroll
        for (int j = 0; j < 4; j++) {
            float2 v = *(float2*)&acc2[i][j];
            int n = n0 + tx * 8 + 2 * j;
            float o0 = v.x + bias[n];
            float o1 = v.y + bias[n + 1];
            if (EPI) {
                o0 = sAv * o0 + (1.0f - sAv) * xres[(size_t)m * FF + n];
                o1 = sAv * o1 + (1.0f - sAv) * xres[(size_t)m * FF + n + 1];
                o0 = fmaxf(o0, 0.0f);
                o1 = fmaxf(o1, 0.0f);
            }
            C[(size_t)m * Nc + n] = o0;
            C[(size_t)m * Nc + n + 1] = o1;
        }
    }
#endif
}

// ---------------- fused edge attention: one warp per (dst type, dst node) ----------------
__global__ void __launch_bounds__(256) attn_kernel(const float* __restrict__ pr_l)
{
    int w = (blockIdx.x * 256 + threadIdx.x) >> 5;
    if (w >= 2 * NN) return;
    const int dt = (w >= NN) ? 1 : 0;
    const int node = w - dt * NN;
    const int et = 1 - dt;
    const float* kqv_d = g_kqv + (size_t)dt * NP * 768;
    const float* kqv_s = g_kqv + (size_t)et * NP * 768;
    const int* off = g_off + et * (NP + 1);
    const int* srt = g_srt + et * EE;
    float* agg = g_agg + (size_t)dt * NP * FF;

    const int lane = threadIdx.x & 31;
    const int h = lane >> 2;
    const int co = h * 32 + (lane & 3) * 8;

    const float* qr = kqv_d + (size_t)node * 768 + 256 + co;
    float4 q0 = *(const float4*)qr;
    float4 q1 = *(const float4*)(qr + 4);
    const float ph = pr_l[et * HH + h] * 0.17677669529663688110f;

    float m = -INFINITY, z = 0.0f;
    float4 a0 = {0.f, 0.f, 0.f, 0.f};
    float4 a1 = {0.f, 0.f, 0.f, 0.f};

    const int b = off[node], e2 = off[node + 1];
    for (int j = b; j < e2; j++) {
        int s = srt[j];
        const float* kr = kqv_s + (size_t)s * 768 + co;
        const float* vr = kr + 512;
        float4 k0 = *(const float4*)kr;
        float4 k1 = *(const float4*)(kr + 4);
        float4 v0 = *(const float4*)vr;
        float4 v1 = *(const float4*)(vr + 4);

        float dot = q0.x * k0.x + q0.y * k0.y + q0.z * k0.z + q0.w * k0.w
                  + q1.x * k1.x + q1.y * k1.y + q1.z * k1.z + q1.w * k1.w;
        dot += __shfl_xor_sync(0xffffffffu, dot, 1);
        dot += __shfl_xor_sync(0xffffffffu, dot, 2);
        float sc = dot * ph;

        float nm = fmaxf(m, sc);
        float scale = __expf(m - nm);
        float ea = __expf(sc - nm);
        z = z * scale + ea;
        a0.x = a0.x * scale + ea * v0.x;  a0.y = a0.y * scale + ea * v0.y;
        a0.z = a0.z * scale + ea * v0.z;  a0.w = a0.w * scale + ea * v0.w;
        a1.x = a1.x * scale + ea * v1.x;  a1.y = a1.y * scale + ea * v1.y;
        a1.z = a1.z * scale + ea * v1.z;  a1.w = a1.w * scale + ea * v1.w;
        m = nm;
    }

    float inv = (z > 0.0f) ? 1.0f / z : 0.0f;
    float* ar = agg + (size_t)node * 256 + co;
    *(float4*)ar       = make_float4(a0.x * inv, a0.y * inv, a0.z * inv, a0.w * inv);
    *(float4*)(ar + 4) = make_float4(a1.x * inv, a1.y * inv, a1.z * inv, a1.w * inv);
}

// ---------------- driver ----------------
extern "C" void kernel_launch(void* const* d_in, const int* in_sizes, int n_in,
                              void* d_out, int out_size)
{
    const float* x0 = (const float*)d_in[0];
    const float* x1 = (const float*)d_in[1];
    const int*   e_dr = (const int*)d_in[2];
    const int*   e_rd = (const int*)d_in[3];
    const float* Wk = (const float*)d_in[4];
    const float* bk = (const float*)d_in[5];
    const float* Ar = (const float*)d_in[6];
    const float* Mr = (const float*)d_in[7];
    const float* pr = (const float*)d_in[8];
    const float* Wo = (const float*)d_in[9];
    const float* bo = (const float*)d_in[10];
    const float* sk = (const float*)d_in[11];
    float* out = (float*)d_out;

    float *gx, *gkqv, *gagg, *gWeT, *gWoT, *gbe;
    cudaGetSymbolAddress((void**)&gx,   g_x);
    cudaGetSymbolAddress((void**)&gkqv, g_kqv);
    cudaGetSymbolAddress((void**)&gagg, g_agg);
    cudaGetSymbolAddress((void**)&gWeT, g_WeT);
    cudaGetSymbolAddress((void**)&gWoT, g_WoT);
    cudaGetSymbolAddress((void**)&gbe,  g_be);

    cudaFuncSetAttribute(gemm_kernel<false, false>, cudaFuncAttributeMaxDynamicSharedMemorySize, SMEM_DYN);
    cudaFuncSetAttribute(gemm_kernel<true, true>,  cudaFuncAttributeMaxDynamicSharedMemorySize, SMEM_DYN);

    const int copyBlocks = (NN * FF + 255) / 256;
    copy_in_kernel<<<copyBlocks, 256>>>(x0, x1);

    fold_kernel<<<96, 256>>>(Wk, bk, Ar, Mr);
    foldq_kernel<<<(2 * 6 * 256 * 256 + 255) / 256, 256>>>(Wk, bk, Wo);

    csr_zero_kernel<<<(2 * NP + 255) / 256, 256>>>();
    csr_hist_kernel<<<(EE + 255) / 256, 256>>>(e_dr + EE, e_rd + EE);
    csr_scan_kernel<<<2, 1024>>>();
    csr_scatter_kernel<<<(EE + 255) / 256, 256>>>(e_dr + EE, e_rd + EE);
    csr_sort_kernel<<<(2 * NP + 255) / 256, 256>>>(e_dr, e_rd);

    for (int l = 0; l < LL; l++) {
        // kqv = x @ W_eff^T + b_eff  -> [ke|q|ve]
        gemm_kernel<false, false><<<dim3(6, NP / 128, 2), 256, SMEM_DYN>>>(
            gx, gWeT + (size_t)l * 2 * 768 * 256, gbe + (size_t)l * 2 * 768, gkqv,
            768, (size_t)NP * FF, (size_t)768 * 256, (size_t)768, (size_t)NP * 768,
            nullptr, nullptr);

        attn_kernel<<<(2 * NN * 32 + 255) / 256, 256>>>(pr + (size_t)l * 2 * HH);

        // x = relu( a*(gelu(agg) @ Wo^T + bo) + (1-a)*x )
        gemm_kernel<true, true><<<dim3(2, NP / 128, 2), 256, SMEM_DYN>>>(
            gagg, gWoT + (size_t)l * 2 * 256 * 256, bo + (size_t)l * 2 * FF, gx,
            256, (size_t)NP * FF, (size_t)256 * 256, (size_t)256, (size_t)NP * FF,
            gx, sk + l * 2);
    }

    copy_out_kernel<<<copyBlocks, 256>>>(out);
}